// round 6
// baseline (speedup 1.0000x reference)
#include <cuda_runtime.h>
#include <math.h>
#include <stdint.h>

// Problem constants
#define HDIM 768
#define DDIM 128
#define BATCH 64
#define SQ 128
#define SD 1024
#define NTOK_Q (BATCH * SQ)   // 8192
#define NTOK_D (BATCH * SD)   // 65536
#define NJCHUNK 8             // SD / 128

#define KC 32                 // K chunk (floats)
#define LDK 36                // smem row stride words (9x16B -> conflict-free ldmatrix)
#define NSTAGE 3

// proj: block tile 256(M) x 128(N)
#define BM 256
#define NBLK_Q (NTOK_Q / BM)  // 32
#define NBLK_D (NTOK_D / BM)  // 256
#define ASTAGE (BM * LDK * 4)        // 36864
#define BSTAGE (128 * LDK * 4)       // 18432
#define RING_OFF 1024
#define PROJ_SMEM (RING_OFF + NSTAGE * (ASTAGE + BSTAGE))   // 166912

// maxsim: block tile 128 x 128
#define MS_SMEM (RING_OFF + NSTAGE * 2 * BSTAGE)            // 111616

// Scratch (device globals: allocation-free per harness rules)
__device__ float g_q_emb[NTOK_Q * DDIM];            // 4 MB
__device__ float g_d_emb[(size_t)NTOK_D * DDIM];    // 32 MB
__device__ float g_pmax[BATCH * NJCHUNK * SQ];      // 256 KB
__device__ float g_w_rna[DDIM * HDIM];              // 384 KB (tf32-rounded W)
__device__ int   g_cnt[BATCH];                      // arrival counters (reset after use)

// ---------------------------------------------------------------------------
// helpers
// ---------------------------------------------------------------------------
__device__ __forceinline__ uint32_t s2u(const void* p) {
    return (uint32_t)__cvta_generic_to_shared(p);
}
__device__ __forceinline__ float f2tff(float x) {
    uint32_t u; asm("cvt.rna.tf32.f32 %0, %1;" : "=r"(u) : "f"(x));
    return __uint_as_float(u);
}
__device__ __forceinline__ void cp16(uint32_t smem, const void* g) {
    asm volatile("cp.async.cg.shared.global [%0], [%1], 16;" :: "r"(smem), "l"(g));
}
#define CP_COMMIT() asm volatile("cp.async.commit_group;" ::: "memory")
#define CP_WAIT(n)  asm volatile("cp.async.wait_group %0;" :: "n"(n) : "memory")

__device__ __forceinline__ void ldsm4(uint32_t& r0, uint32_t& r1, uint32_t& r2,
                                      uint32_t& r3, uint32_t addr) {
    asm volatile("ldmatrix.sync.aligned.m8n8.x4.shared.b16 {%0,%1,%2,%3}, [%4];"
                 : "=r"(r0), "=r"(r1), "=r"(r2), "=r"(r3) : "r"(addr));
}
__device__ __forceinline__ void mma8(float c[4], const uint32_t a[4], const uint32_t b[2]) {
    asm volatile("mma.sync.aligned.m16n8k8.row.col.f32.tf32.tf32.f32 "
                 "{%0,%1,%2,%3}, {%4,%5,%6,%7}, {%8,%9}, {%0,%1,%2,%3};"
                 : "+f"(c[0]), "+f"(c[1]), "+f"(c[2]), "+f"(c[3])
                 : "r"(a[0]), "r"(a[1]), "r"(a[2]), "r"(a[3]),
                   "r"(b[0]), "r"(b[1]));
}

// ---------------------------------------------------------------------------
// Kernel 0: tf32-round W once (makes the W operand exact under in-MMA RZ).
// ---------------------------------------------------------------------------
__global__ __launch_bounds__(256) void round_w(const float* __restrict__ W)
{
    int i = blockIdx.x * 256 + threadIdx.x;
    float4 v = ((const float4*)W)[i];
    v.x = f2tff(v.x); v.y = f2tff(v.y); v.z = f2tff(v.z); v.w = f2tff(v.w);
    ((float4*)g_w_rna)[i] = v;
}

// ---------------------------------------------------------------------------
// Kernel 1: projection + L2 normalize.  Block tile 256x128, 8 warps 4m x 2n,
// each warp covers TWO M-halves (rows warpM.. and 128+warpM..) reusing its B
// fragments in registers -> smem read traffic per 128 rows: 96KB -> 64KB.
// 3-stage cp.async ring, KC=32.  Mask folded into epilogue scale; embeddings
// written tf32-rounded so the maxsim MMA is lossless.
// ---------------------------------------------------------------------------
__global__ __launch_bounds__(256, 1) void proj_tc(
    const float* __restrict__ Xq, const int* __restrict__ Mq,
    const float* __restrict__ Xd, const int* __restrict__ Md,
    float* __restrict__ Eq, float* __restrict__ Ed)
{
    extern __shared__ char smem[];
    const uint32_t sbase = s2u(smem);
    const int tid  = threadIdx.x;
    const int lane = tid & 31;
    const int warp = tid >> 5;

    const bool isQ = blockIdx.x < NBLK_Q;
    const int  rb  = isQ ? blockIdx.x : (blockIdx.x - NBLK_Q);
    const int  row0 = rb * BM;
    const float* X = isQ ? Xq : Xd;
    const int*   M = isQ ? Mq : Md;
    float*       E = isQ ? Eq : Ed;
    const float* gA = X + (size_t)row0 * HDIM;
    const float* gB = g_w_rna;

    const int warpM = (warp & 3) * 32;
    const int warpN = (warp >> 2) * 64;
    const int wn = warp >> 2;
    const int g = lane >> 2, tig = lane & 3;
    const int l7 = lane & 7, b3 = (lane >> 3) & 1, b4 = (lane >> 4) & 1;

    uint32_t aOff[2][2], bOff[4];
#pragma unroll
    for (int h = 0; h < 2; h++)
#pragma unroll
        for (int i = 0; i < 2; i++)
            aOff[h][i] = (uint32_t)((h * 128 + warpM + i * 16 + l7 + b3 * 8) * LDK + b4 * 4);
#pragma unroll
    for (int jj = 0; jj < 4; jj++)
        bOff[jj] = (uint32_t)((warpN + jj * 16 + b4 * 8 + l7) * LDK + b3 * 4);

    float acc[2][2][8][4];
#pragma unroll
    for (int h = 0; h < 2; h++)
#pragma unroll
        for (int i = 0; i < 2; i++)
#pragma unroll
            for (int j = 0; j < 8; j++)
#pragma unroll
                for (int e = 0; e < 4; e++) acc[h][i][j][e] = 0.f;

    // ring bases
    const uint32_t aRing = sbase + RING_OFF;
    const uint32_t bRing = sbase + RING_OFF + NSTAGE * ASTAGE;

    // stage loader: A 2048 float4 (8/thr), B 1024 float4 (4/thr)
    auto load_stage = [&](int st, int kchunk) {
        const float* a = gA + kchunk * KC;
        const float* b = gB + kchunk * KC;
        const uint32_t smA = aRing + (uint32_t)st * ASTAGE;
        const uint32_t smB = bRing + (uint32_t)st * BSTAGE;
#pragma unroll
        for (int i = 0; i < 8; i++) {
            int idx = tid + i * 256;     // [0,2048)
            int r = idx >> 3;            // [0,256)
            int kq = (idx & 7) * 4;
            cp16(smA + (uint32_t)(r * LDK + kq) * 4, a + (size_t)r * HDIM + kq);
        }
#pragma unroll
        for (int i = 0; i < 4; i++) {
            int idx = tid + i * 256;     // [0,1024)
            int r = idx >> 3;            // [0,128)
            int kq = (idx & 7) * 4;
            cp16(smB + (uint32_t)(r * LDK + kq) * 4, b + (size_t)r * HDIM + kq);
        }
    };

    // prologue: stages 0,1
    load_stage(0, 0); CP_COMMIT();
    load_stage(1, 1); CP_COMMIT();

    const int NC = HDIM / KC;   // 24
    int st = 0, stn = 2;
    for (int k = 0; k < NC; k++) {
        CP_WAIT(1);
        __syncthreads();
        const int m = k + 2;
        if (m < NC) { load_stage(stn, m); CP_COMMIT(); }

        const uint32_t aB = aRing + (uint32_t)st * ASTAGE;
        const uint32_t bB = bRing + (uint32_t)st * BSTAGE;
#pragma unroll
        for (int ks = 0; ks < 4; ks++) {
            const int k8 = ks * 8;
            uint32_t af[2][2][4], bf[8][2];
#pragma unroll
            for (int jj = 0; jj < 4; jj++) {
                uint32_t r0, r1, r2, r3;
                ldsm4(r0, r1, r2, r3, bB + (bOff[jj] + k8) * 4);
                bf[2 * jj][0] = r0;  bf[2 * jj][1] = r1;
                bf[2 * jj + 1][0] = r2;  bf[2 * jj + 1][1] = r3;
            }
#pragma unroll
            for (int h = 0; h < 2; h++)
#pragma unroll
                for (int i = 0; i < 2; i++)
                    ldsm4(af[h][i][0], af[h][i][1], af[h][i][2], af[h][i][3],
                          aB + (aOff[h][i] + k8) * 4);
#pragma unroll
            for (int h = 0; h < 2; h++)
#pragma unroll
                for (int i = 0; i < 2; i++)
#pragma unroll
                    for (int j = 0; j < 8; j++) mma8(acc[h][i][j], af[h][i], bf[j]);
        }
        st = (st + 1 == NSTAGE) ? 0 : st + 1;
        stn = (stn + 1 == NSTAGE) ? 0 : stn + 1;
    }
    __syncthreads();   // smem reads done; reuse ring for reductions

    // ---- fused L2 normalize (mask folded into scale) ----
    float* ssb = (float*)(smem + RING_OFF);   // [2][256]
#pragma unroll
    for (int h = 0; h < 2; h++)
#pragma unroll
        for (int i = 0; i < 2; i++) {
            float sl = 0.f, sh = 0.f;
#pragma unroll
            for (int j = 0; j < 8; j++) {
                sl += acc[h][i][j][0] * acc[h][i][j][0] + acc[h][i][j][1] * acc[h][i][j][1];
                sh += acc[h][i][j][2] * acc[h][i][j][2] + acc[h][i][j][3] * acc[h][i][j][3];
            }
            sl += __shfl_xor_sync(0xffffffffu, sl, 1);
            sl += __shfl_xor_sync(0xffffffffu, sl, 2);
            sh += __shfl_xor_sync(0xffffffffu, sh, 1);
            sh += __shfl_xor_sync(0xffffffffu, sh, 2);
            if (tig == 0) {
                const int r = h * 128 + warpM + i * 16 + g;
                ssb[wn * 256 + r]     = sl;
                ssb[wn * 256 + r + 8] = sh;
            }
        }
    __syncthreads();
#pragma unroll
    for (int h = 0; h < 2; h++)
#pragma unroll
        for (int i = 0; i < 2; i++) {
            const int rl = h * 128 + warpM + i * 16 + g;
            const int rh = rl + 8;
            const float tl = ssb[rl] + ssb[256 + rl];
            const float th = ssb[rh] + ssb[256 + rh];
            const float scl = (float)M[row0 + rl] / fmaxf(sqrtf(tl), 1e-12f);
            const float sch = (float)M[row0 + rh] / fmaxf(sqrtf(th), 1e-12f);
#pragma unroll
            for (int j = 0; j < 8; j++) {
                float2 v;
                v.x = f2tff(acc[h][i][j][0] * scl); v.y = f2tff(acc[h][i][j][1] * scl);
                *(float2*)&E[(size_t)(row0 + rl) * DDIM + warpN + j * 8 + tig * 2] = v;
                v.x = f2tff(acc[h][i][j][2] * sch); v.y = f2tff(acc[h][i][j][3] * sch);
                *(float2*)&E[(size_t)(row0 + rh) * DDIM + warpN + j * 8 + tig * 2] = v;
            }
        }
}

// ---------------------------------------------------------------------------
// Kernel 2: per-batch similarity + partial max + fused finalize.
// Block (b, jc): [128 q x 128 docs], K = 128 (4 chunks of 32).
// Last-arriving block per batch reduces g_pmax -> out[b].
// ---------------------------------------------------------------------------
__global__ __launch_bounds__(256, 2) void maxsim_tc(float* __restrict__ out)
{
    extern __shared__ char smem[];
    const uint32_t sbase = s2u(smem);
    const int tid  = threadIdx.x;
    const int lane = tid & 31;
    const int warp = tid >> 5;
    const int b  = blockIdx.x;
    const int jc = blockIdx.y;

    const float* q = g_q_emb + (size_t)b * SQ * DDIM;
    const float* d = g_d_emb + ((size_t)b * SD + (size_t)jc * 128) * DDIM;

    const int warpM = (warp & 3) * 32;
    const int warpN = (warp >> 2) * 64;
    const int wn = warp >> 2;
    const int g = lane >> 2, tig = lane & 3;
    const int l7 = lane & 7, b3 = (lane >> 3) & 1, b4 = (lane >> 4) & 1;

    uint32_t aOff[2], bOff[4];
#pragma unroll
    for (int i = 0; i < 2; i++)
        aOff[i] = (uint32_t)((warpM + i * 16 + l7 + b3 * 8) * LDK + b4 * 4);
#pragma unroll
    for (int jj = 0; jj < 4; jj++)
        bOff[jj] = (uint32_t)((warpN + jj * 16 + b4 * 8 + l7) * LDK + b3 * 4);

    float acc[2][8][4];
#pragma unroll
    for (int i = 0; i < 2; i++)
#pragma unroll
        for (int j = 0; j < 8; j++)
#pragma unroll
            for (int e = 0; e < 4; e++) acc[i][j][e] = 0.f;

    const uint32_t aRing = sbase + RING_OFF;
    const uint32_t bRing = sbase + RING_OFF + NSTAGE * BSTAGE;

    auto load_stage = [&](int st, int kchunk) {
        const float* a = q + kchunk * KC;
        const float* dd = d + kchunk * KC;
        const uint32_t smA = aRing + (uint32_t)st * BSTAGE;
        const uint32_t smB = bRing + (uint32_t)st * BSTAGE;
#pragma unroll
        for (int i = 0; i < 4; i++) {
            int idx = tid + i * 256;
            int r = idx >> 3;
            int kq = (idx & 7) * 4;
            uint32_t off = (uint32_t)(r * LDK + kq) * 4;
            cp16(smA + off, a + (size_t)r * DDIM + kq);
            cp16(smB + off, dd + (size_t)r * DDIM + kq);
        }
    };

    load_stage(0, 0); CP_COMMIT();
    load_stage(1, 1); CP_COMMIT();

    const int NC = DDIM / KC;   // 4
    int st = 0, stn = 2;
    for (int k = 0; k < NC; k++) {
        CP_WAIT(1);
        __syncthreads();
        const int m = k + 2;
        if (m < NC) { load_stage(stn, m); CP_COMMIT(); }

        const uint32_t aB = aRing + (uint32_t)st * BSTAGE;
        const uint32_t bB = bRing + (uint32_t)st * BSTAGE;
#pragma unroll
        for (int ks = 0; ks < 4; ks++) {
            const int k8 = ks * 8;
            uint32_t af[2][4], bf[8][2];
#pragma unroll
            for (int i = 0; i < 2; i++)
                ldsm4(af[i][0], af[i][1], af[i][2], af[i][3], aB + (aOff[i] + k8) * 4);
#pragma unroll
            for (int jj = 0; jj < 4; jj++) {
                uint32_t r0, r1, r2, r3;
                ldsm4(r0, r1, r2, r3, bB + (bOff[jj] + k8) * 4);
                bf[2 * jj][0] = r0;  bf[2 * jj][1] = r1;
                bf[2 * jj + 1][0] = r2;  bf[2 * jj + 1][1] = r3;
            }
#pragma unroll
            for (int i = 0; i < 2; i++)
#pragma unroll
                for (int j = 0; j < 8; j++) mma8(acc[i][j], af[i], bf[j]);
        }
        st = (st + 1 == NSTAGE) ? 0 : st + 1;
        stn = (stn + 1 == NSTAGE) ? 0 : stn + 1;
    }
    __syncthreads();

    // ---- row max over this 128-doc chunk ----
    float* mxb = (float*)(smem + RING_OFF);   // [2][128]
#pragma unroll
    for (int i = 0; i < 2; i++) {
        float ml = acc[i][0][0], mh = acc[i][0][2];
#pragma unroll
        for (int j = 0; j < 8; j++) {
            ml = fmaxf(ml, fmaxf(acc[i][j][0], acc[i][j][1]));
            mh = fmaxf(mh, fmaxf(acc[i][j][2], acc[i][j][3]));
        }
        ml = fmaxf(ml, __shfl_xor_sync(0xffffffffu, ml, 1));
        ml = fmaxf(ml, __shfl_xor_sync(0xffffffffu, ml, 2));
        mh = fmaxf(mh, __shfl_xor_sync(0xffffffffu, mh, 1));
        mh = fmaxf(mh, __shfl_xor_sync(0xffffffffu, mh, 2));
        if (tig == 0) {
            mxb[wn * 128 + warpM + i * 16 + g]     = ml;
            mxb[wn * 128 + warpM + i * 16 + 8 + g] = mh;
        }
    }
    __syncthreads();
    if (tid < 128)
        g_pmax[((size_t)b * NJCHUNK + jc) * SQ + tid] =
            fmaxf(mxb[tid], mxb[128 + tid]);

    // ---- fused finalize: last-arriving block of this batch reduces ----
    __threadfence();
    __shared__ int lastflag;
    if (tid == 0) {
        int old = atomicAdd(&g_cnt[b], 1);
        lastflag = (old == NJCHUNK - 1);
    }
    __syncthreads();
    if (lastflag) {
        __threadfence();
        if (tid < 128) {
            float m = g_pmax[((size_t)b * NJCHUNK + 0) * SQ + tid];
#pragma unroll
            for (int c = 1; c < NJCHUNK; c++)
                m = fmaxf(m, g_pmax[((size_t)b * NJCHUNK + c) * SQ + tid]);
#pragma unroll
            for (int o = 16; o > 0; o >>= 1)
                m += __shfl_xor_sync(0xffffffffu, m, o, 32);
            float* s = (float*)(smem + RING_OFF);
            if ((tid & 31) == 0) s[tid >> 5] = m;
            __syncwarp();
            if (tid == 0) {
                // wait for the 4 warp partials via block sync below is not
                // possible inside divergent path for >128 threads; use
                // named-barrier-free approach: tid<128 all reach here.
            }
        }
        __syncthreads();
        if (tid == 0) {
            float* s = (float*)(smem + RING_OFF);
            out[b] = s[0] + s[1] + s[2] + s[3];
            g_cnt[b] = 0;     // reset for next graph replay
        }
    }
}

// ---------------------------------------------------------------------------
extern "C" void kernel_launch(void* const* d_in, const int* in_sizes, int n_in,
                              void* d_out, int out_size)
{
    const float* qh = (const float*)d_in[0];   // [64,128,768]
    const int*   qm = (const int*)  d_in[1];   // [64,128]
    const float* dh = (const float*)d_in[2];   // [64,1024,768]
    const int*   dm = (const int*)  d_in[3];   // [64,1024]
    const float* W  = (const float*)d_in[4];   // [128,768]
    float* out = (float*)d_out;                // [64]

    float *gq = nullptr, *gd = nullptr;
    cudaGetSymbolAddress((void**)&gq, g_q_emb);
    cudaGetSymbolAddress((void**)&gd, g_d_emb);

    cudaFuncSetAttribute(proj_tc, cudaFuncAttributeMaxDynamicSharedMemorySize, PROJ_SMEM);
    cudaFuncSetAttribute(maxsim_tc, cudaFuncAttributeMaxDynamicSharedMemorySize, MS_SMEM);

    round_w<<<(DDIM * HDIM / 4) / 256, 256>>>(W);
    proj_tc<<<NBLK_Q + NBLK_D, 256, PROJ_SMEM>>>(qh, qm, dh, dm, gq, gd);
    maxsim_tc<<<dim3(BATCH, NJCHUNK), 256, MS_SMEM>>>(out);
}

// round 7
// speedup vs baseline: 1.0345x; 1.0345x over previous
#include <cuda_runtime.h>
#include <math.h>
#include <stdint.h>

// Problem constants
#define HDIM 768
#define DDIM 128
#define BATCH 64
#define SQ 128
#define SD 1024
#define NTOK_Q (BATCH * SQ)   // 8192
#define NTOK_D (BATCH * SD)   // 65536
#define NJCHUNK 8             // SD / 128
#define NBLK_Q (NTOK_Q / 128) // 64
#define NBLK_D (NTOK_D / 128) // 512

#define KC 32                 // K chunk (floats)
#define LDK 36                // smem row stride words (9x16B -> conflict-free ldmatrix)
#define NSTAGE 3
#define STAGE_BYTES (128 * LDK * 4)      // 18432
#define RING_OFF 1024
#define SMEM_BYTES (RING_OFF + 2 * NSTAGE * STAGE_BYTES)   // 111616

// Scratch (device globals: allocation-free per harness rules)
__device__ float g_q_emb[NTOK_Q * DDIM];            // 4 MB
__device__ float g_d_emb[(size_t)NTOK_D * DDIM];    // 32 MB
__device__ float g_pmax[BATCH * NJCHUNK * SQ];      // 256 KB
__device__ float g_w_rna[DDIM * HDIM];              // 384 KB (tf32-rounded W)
__device__ int   g_cnt[BATCH];                      // arrival counters (reset after use)

// ---------------------------------------------------------------------------
// helpers
// ---------------------------------------------------------------------------
__device__ __forceinline__ uint32_t s2u(const void* p) {
    return (uint32_t)__cvta_generic_to_shared(p);
}
__device__ __forceinline__ float f2tff(float x) {
    uint32_t u; asm("cvt.rna.tf32.f32 %0, %1;" : "=r"(u) : "f"(x));
    return __uint_as_float(u);
}
__device__ __forceinline__ void cp16(uint32_t smem, const void* g) {
    asm volatile("cp.async.cg.shared.global [%0], [%1], 16;" :: "r"(smem), "l"(g));
}
#define CP_COMMIT() asm volatile("cp.async.commit_group;" ::: "memory")
#define CP_WAIT(n)  asm volatile("cp.async.wait_group %0;" :: "n"(n) : "memory")

__device__ __forceinline__ void ldsm4(uint32_t& r0, uint32_t& r1, uint32_t& r2,
                                      uint32_t& r3, uint32_t addr) {
    asm volatile("ldmatrix.sync.aligned.m8n8.x4.shared.b16 {%0,%1,%2,%3}, [%4];"
                 : "=r"(r0), "=r"(r1), "=r"(r2), "=r"(r3) : "r"(addr));
}
__device__ __forceinline__ void mma8(float c[4], const uint32_t a[4], const uint32_t b[2]) {
    asm volatile("mma.sync.aligned.m16n8k8.row.col.f32.tf32.tf32.f32 "
                 "{%0,%1,%2,%3}, {%4,%5,%6,%7}, {%8,%9}, {%0,%1,%2,%3};"
                 : "+f"(c[0]), "+f"(c[1]), "+f"(c[2]), "+f"(c[3])
                 : "r"(a[0]), "r"(a[1]), "r"(a[2]), "r"(a[3]),
                   "r"(b[0]), "r"(b[1]));
}

// Load one KC=32 chunk of A and B tiles into ring stage st via cp.async.
__device__ __forceinline__ void load_stage(uint32_t sbase, int st,
                                           const float* gA, const float* gB,
                                           int strideA, int strideB, int tid)
{
    const uint32_t smA = sbase + RING_OFF + (uint32_t)st * STAGE_BYTES;
    const uint32_t smB = smA + NSTAGE * STAGE_BYTES;
#pragma unroll
    for (int i = 0; i < 4; i++) {
        int idx = tid + i * 256;        // [0,1024)
        int r = idx >> 3;               // [0,128)
        int kq = (idx & 7) * 4;         // {0,4,...,28}
        uint32_t off = (uint32_t)(r * LDK + kq) * 4;
        cp16(smA + off, gA + (size_t)r * strideA + kq);
        cp16(smB + off, gB + (size_t)r * strideB + kq);
    }
}

// Consume one KC=32 stage: 4 k8 steps, each 6 ldmatrix.x4 + 16 mma per warp.
__device__ __forceinline__ void consume_stage(uint32_t sbase, int st,
                                              const uint32_t aOff[2],
                                              const uint32_t bOff[4],
                                              float acc[2][8][4])
{
    const uint32_t aB = sbase + RING_OFF + (uint32_t)st * STAGE_BYTES;
    const uint32_t bB = aB + NSTAGE * STAGE_BYTES;
#pragma unroll
    for (int ks = 0; ks < 4; ks++) {
        const int k8 = ks * 8;
        uint32_t af[2][4], bf[8][2];
#pragma unroll
        for (int i = 0; i < 2; i++)
            ldsm4(af[i][0], af[i][1], af[i][2], af[i][3], aB + (aOff[i] + k8) * 4);
#pragma unroll
        for (int jj = 0; jj < 4; jj++) {
            uint32_t r0, r1, r2, r3;
            ldsm4(r0, r1, r2, r3, bB + (bOff[jj] + k8) * 4);
            bf[2 * jj][0] = r0;  bf[2 * jj][1] = r1;
            bf[2 * jj + 1][0] = r2;  bf[2 * jj + 1][1] = r3;
        }
#pragma unroll
        for (int i = 0; i < 2; i++)
#pragma unroll
            for (int j = 0; j < 8; j++) mma8(acc[i][j], af[i], bf[j]);
    }
}

__device__ __forceinline__ void frag_offsets(int warp, int lane,
                                             uint32_t aOff[2], uint32_t bOff[4],
                                             int& warpM, int& warpN)
{
    warpM = (warp & 3) * 32;
    warpN = (warp >> 2) * 64;
    const int l7 = lane & 7, b3 = (lane >> 3) & 1, b4 = (lane >> 4) & 1;
#pragma unroll
    for (int i = 0; i < 2; i++)
        aOff[i] = (uint32_t)((warpM + i * 16 + l7 + b3 * 8) * LDK + b4 * 4);
#pragma unroll
    for (int jj = 0; jj < 4; jj++)
        bOff[jj] = (uint32_t)((warpN + jj * 16 + b4 * 8 + l7) * LDK + b3 * 4);
}

// ---------------------------------------------------------------------------
// Kernel 0: tf32-round W once (makes the W operand exact under in-MMA RZ).
// ---------------------------------------------------------------------------
__global__ __launch_bounds__(256) void round_w(const float* __restrict__ W)
{
    int i = blockIdx.x * 256 + threadIdx.x;     // float4 index
    float4 v = ((const float4*)W)[i];
    v.x = f2tff(v.x); v.y = f2tff(v.y); v.z = f2tff(v.z); v.w = f2tff(v.w);
    ((float4*)g_w_rna)[i] = v;
}

// ---------------------------------------------------------------------------
// Kernel 1: projection + L2 normalize (tf32 mma.sync, 3-stage KC=32 ring).
// Block tile 128x128, 8 warps 4m x 2n, 2 blocks/SM.  Mask folded into the
// epilogue scale; embeddings written tf32-rounded (maxsim MMA is lossless).
// ---------------------------------------------------------------------------
__global__ __launch_bounds__(256, 2) void proj_tc(
    const float* __restrict__ Xq, const int* __restrict__ Mq,
    const float* __restrict__ Xd, const int* __restrict__ Md,
    float* __restrict__ Eq, float* __restrict__ Ed)
{
    extern __shared__ char smem[];
    const uint32_t sbase = s2u(smem);
    const int tid  = threadIdx.x;
    const int lane = tid & 31;
    const int warp = tid >> 5;

    const bool isQ = blockIdx.x < NBLK_Q;
    const int  rb  = isQ ? blockIdx.x : (blockIdx.x - NBLK_Q);
    const int  row0 = rb * 128;
    const float* X = isQ ? Xq : Xd;
    const int*   M = isQ ? Mq : Md;
    float*       E = isQ ? Eq : Ed;
    const float* gA = X + (size_t)row0 * HDIM;
    const float* gB = g_w_rna;

    uint32_t aOff[2], bOff[4];
    int warpM, warpN;
    frag_offsets(warp, lane, aOff, bOff, warpM, warpN);
    const int wn = warp >> 2;
    const int g = lane >> 2, tig = lane & 3;

    float acc[2][8][4];
#pragma unroll
    for (int i = 0; i < 2; i++)
#pragma unroll
        for (int j = 0; j < 8; j++)
#pragma unroll
            for (int e = 0; e < 4; e++) acc[i][j][e] = 0.f;

    // prologue: stages 0,1
#pragma unroll
    for (int s = 0; s < 2; s++) {
        load_stage(sbase, s, gA + s * KC, gB + s * KC, HDIM, HDIM, tid);
        CP_COMMIT();
    }

    const int NC = HDIM / KC;   // 24
    int st = 0, stn = 2;
    for (int k = 0; k < NC; k++) {
        CP_WAIT(1);
        __syncthreads();
        const int m = k + 2;
        if (m < NC) {
            load_stage(sbase, stn, gA + m * KC, gB + m * KC, HDIM, HDIM, tid);
            CP_COMMIT();
        }
        consume_stage(sbase, st, aOff, bOff, acc);
        st = (st + 1 == NSTAGE) ? 0 : st + 1;
        stn = (stn + 1 == NSTAGE) ? 0 : stn + 1;
    }
    __syncthreads();   // smem reads done; reuse ring for reductions

    // ---- fused L2 normalize (mask folded into scale) ----
    float* ssb = (float*)(smem + RING_OFF);   // [2][128]
#pragma unroll
    for (int i = 0; i < 2; i++) {
        float sl = 0.f, sh = 0.f;
#pragma unroll
        for (int j = 0; j < 8; j++) {
            sl += acc[i][j][0] * acc[i][j][0] + acc[i][j][1] * acc[i][j][1];
            sh += acc[i][j][2] * acc[i][j][2] + acc[i][j][3] * acc[i][j][3];
        }
        sl += __shfl_xor_sync(0xffffffffu, sl, 1);
        sl += __shfl_xor_sync(0xffffffffu, sl, 2);
        sh += __shfl_xor_sync(0xffffffffu, sh, 1);
        sh += __shfl_xor_sync(0xffffffffu, sh, 2);
        if (tig == 0) {
            ssb[wn * 128 + warpM + i * 16 + g]     = sl;
            ssb[wn * 128 + warpM + i * 16 + 8 + g] = sh;
        }
    }
    __syncthreads();
#pragma unroll
    for (int i = 0; i < 2; i++) {
        const int rl = warpM + i * 16 + g;
        const int rh = rl + 8;
        const float tl = ssb[rl] + ssb[128 + rl];
        const float th = ssb[rh] + ssb[128 + rh];
        const float scl = (float)M[row0 + rl] / fmaxf(sqrtf(tl), 1e-12f);
        const float sch = (float)M[row0 + rh] / fmaxf(sqrtf(th), 1e-12f);
#pragma unroll
        for (int j = 0; j < 8; j++) {
            float2 v;
            v.x = f2tff(acc[i][j][0] * scl); v.y = f2tff(acc[i][j][1] * scl);
            *(float2*)&E[(size_t)(row0 + rl) * DDIM + warpN + j * 8 + tig * 2] = v;
            v.x = f2tff(acc[i][j][2] * sch); v.y = f2tff(acc[i][j][3] * sch);
            *(float2*)&E[(size_t)(row0 + rh) * DDIM + warpN + j * 8 + tig * 2] = v;
        }
    }
}

// ---------------------------------------------------------------------------
// Kernel 2: per-batch similarity + partial max + fused finalize.
// Block (b, jc): [128 q x 128 docs], K = 128 (4 chunks of 32).
// Last-arriving block per batch reduces g_pmax -> out[b], resets the counter.
// ---------------------------------------------------------------------------
__global__ __launch_bounds__(256, 2) void maxsim_tc(float* __restrict__ out)
{
    extern __shared__ char smem[];
    const uint32_t sbase = s2u(smem);
    const int tid  = threadIdx.x;
    const int lane = tid & 31;
    const int warp = tid >> 5;
    const int b  = blockIdx.x;
    const int jc = blockIdx.y;

    const float* q = g_q_emb + (size_t)b * SQ * DDIM;
    const float* d = g_d_emb + ((size_t)b * SD + (size_t)jc * 128) * DDIM;

    uint32_t aOff[2], bOff[4];
    int warpM, warpN;
    frag_offsets(warp, lane, aOff, bOff, warpM, warpN);
    const int wn = warp >> 2;
    const int g = lane >> 2, tig = lane & 3;

    float acc[2][8][4];
#pragma unroll
    for (int i = 0; i < 2; i++)
#pragma unroll
        for (int j = 0; j < 8; j++)
#pragma unroll
            for (int e = 0; e < 4; e++) acc[i][j][e] = 0.f;

#pragma unroll
    for (int s = 0; s < 2; s++) {
        load_stage(sbase, s, q + s * KC, d + s * KC, DDIM, DDIM, tid);
        CP_COMMIT();
    }

    const int NC = DDIM / KC;   // 4
    int st = 0, stn = 2;
    for (int k = 0; k < NC; k++) {
        CP_WAIT(1);
        __syncthreads();
        const int m = k + 2;
        if (m < NC) {
            load_stage(sbase, stn, q + m * KC, d + m * KC, DDIM, DDIM, tid);
            CP_COMMIT();
        }
        consume_stage(sbase, st, aOff, bOff, acc);
        st = (st + 1 == NSTAGE) ? 0 : st + 1;
        stn = (stn + 1 == NSTAGE) ? 0 : stn + 1;
    }
    __syncthreads();

    // ---- row max over this 128-doc chunk ----
    float* mxb = (float*)(smem + RING_OFF);   // [2][128]
#pragma unroll
    for (int i = 0; i < 2; i++) {
        float ml = acc[i][0][0], mh = acc[i][0][2];
#pragma unroll
        for (int j = 0; j < 8; j++) {
            ml = fmaxf(ml, fmaxf(acc[i][j][0], acc[i][j][1]));
            mh = fmaxf(mh, fmaxf(acc[i][j][2], acc[i][j][3]));
        }
        ml = fmaxf(ml, __shfl_xor_sync(0xffffffffu, ml, 1));
        ml = fmaxf(ml, __shfl_xor_sync(0xffffffffu, ml, 2));
        mh = fmaxf(mh, __shfl_xor_sync(0xffffffffu, mh, 1));
        mh = fmaxf(mh, __shfl_xor_sync(0xffffffffu, mh, 2));
        if (tig == 0) {
            mxb[wn * 128 + warpM + i * 16 + g]     = ml;
            mxb[wn * 128 + warpM + i * 16 + 8 + g] = mh;
        }
    }
    __syncthreads();
    if (tid < 128)
        g_pmax[((size_t)b * NJCHUNK + jc) * SQ + tid] =
            fmaxf(mxb[tid], mxb[128 + tid]);

    // ---- fused finalize: last-arriving block of this batch reduces ----
    __threadfence();
    __shared__ int lastflag;
    if (tid == 0) {
        int old = atomicAdd(&g_cnt[b], 1);
        lastflag = (old == NJCHUNK - 1);
    }
    __syncthreads();
    if (lastflag) {
        __threadfence();
        float* s = (float*)(smem + RING_OFF);
        if (tid < 128) {
            float m = g_pmax[((size_t)b * NJCHUNK + 0) * SQ + tid];
#pragma unroll
            for (int c = 1; c < NJCHUNK; c++)
                m = fmaxf(m, g_pmax[((size_t)b * NJCHUNK + c) * SQ + tid]);
#pragma unroll
            for (int o = 16; o > 0; o >>= 1)
                m += __shfl_xor_sync(0xffffffffu, m, o, 32);
            if ((tid & 31) == 0) s[tid >> 5] = m;
        }
        __syncthreads();
        if (tid == 0) {
            out[b] = s[0] + s[1] + s[2] + s[3];
            g_cnt[b] = 0;     // reset for next graph replay
        }
    }
}

// ---------------------------------------------------------------------------
extern "C" void kernel_launch(void* const* d_in, const int* in_sizes, int n_in,
                              void* d_out, int out_size)
{
    const float* qh = (const float*)d_in[0];   // [64,128,768]
    const int*   qm = (const int*)  d_in[1];   // [64,128]
    const float* dh = (const float*)d_in[2];   // [64,1024,768]
    const int*   dm = (const int*)  d_in[3];   // [64,1024]
    const float* W  = (const float*)d_in[4];   // [128,768]
    float* out = (float*)d_out;                // [64]

    float *gq = nullptr, *gd = nullptr;
    cudaGetSymbolAddress((void**)&gq, g_q_emb);
    cudaGetSymbolAddress((void**)&gd, g_d_emb);

    cudaFuncSetAttribute(proj_tc, cudaFuncAttributeMaxDynamicSharedMemorySize, SMEM_BYTES);
    cudaFuncSetAttribute(maxsim_tc, cudaFuncAttributeMaxDynamicSharedMemorySize, SMEM_BYTES);

    round_w<<<(DDIM * HDIM / 4) / 256, 256>>>(W);
    proj_tc<<<NBLK_Q + NBLK_D, 256, SMEM_BYTES>>>(qh, qm, dh, dm, gq, gd);
    maxsim_tc<<<dim3(BATCH, NJCHUNK), 256, SMEM_BYTES>>>(out);
}

// round 8
// speedup vs baseline: 1.0993x; 1.0626x over previous
#include <cuda_runtime.h>
#include <math.h>
#include <stdint.h>

// Problem constants
#define HDIM 768
#define DDIM 128
#define BATCH 64
#define SQ 128
#define SD 1024
#define NTOK_Q (BATCH * SQ)   // 8192
#define NTOK_D (BATCH * SD)   // 65536
#define NJCHUNK 8             // SD / 128
#define NBLK_Q (NTOK_Q / 128) // 64
#define NBLK_D (NTOK_D / 128) // 512

#define KC 32                 // K chunk (floats)
#define LDK 36                // smem row stride words (9x16B -> conflict-free ldmatrix)
#define NSTAGE 3
#define STAGE_BYTES (128 * LDK * 4)      // 18432
#define RING_OFF 1024
#define SMEM_BYTES (RING_OFF + 2 * NSTAGE * STAGE_BYTES)   // 111616

// Scratch (device globals: allocation-free per harness rules)
__device__ float g_q_emb[NTOK_Q * DDIM];            // 4 MB
__device__ float g_d_emb[(size_t)NTOK_D * DDIM];    // 32 MB
__device__ float g_pmax[BATCH * NJCHUNK * SQ];      // 256 KB
__device__ float g_w_rna[DDIM * HDIM];              // 384 KB (tf32-rounded W)

// ---------------------------------------------------------------------------
// helpers
// ---------------------------------------------------------------------------
__device__ __forceinline__ uint32_t s2u(const void* p) {
    return (uint32_t)__cvta_generic_to_shared(p);
}
__device__ __forceinline__ float f2tff(float x) {
    uint32_t u; asm("cvt.rna.tf32.f32 %0, %1;" : "=r"(u) : "f"(x));
    return __uint_as_float(u);
}
__device__ __forceinline__ void cp16(uint32_t smem, const void* g) {
    asm volatile("cp.async.cg.shared.global [%0], [%1], 16;" :: "r"(smem), "l"(g));
}
#define CP_COMMIT() asm volatile("cp.async.commit_group;" ::: "memory")
#define CP_WAIT(n)  asm volatile("cp.async.wait_group %0;" :: "n"(n) : "memory")

#define MBARRIER_INIT(mb, n) \
    asm volatile("mbarrier.init.shared.b64 [%0], %1;" :: "r"((uint32_t)(mb)), "r"((uint32_t)(n)) : "memory")
#define MBARRIER_ARRIVE(mb) \
    asm volatile("mbarrier.arrive.shared.b64 _, [%0];" :: "r"((uint32_t)(mb)) : "memory")

__device__ __forceinline__ void mbar_wait(uint32_t mb, uint32_t parity) {
    uint32_t done;
    asm volatile("{\n\t.reg .pred p;\n\t"
                 "mbarrier.try_wait.parity.acquire.cta.shared::cta.b64 p, [%1], %2;\n\t"
                 "selp.b32 %0, 1, 0, p;\n\t}" : "=r"(done) : "r"(mb), "r"(parity) : "memory");
    while (!done) {
        asm volatile("{\n\t.reg .pred p;\n\t"
                     "mbarrier.try_wait.parity.acquire.cta.shared::cta.b64 p, [%1], %2, 0x989680;\n\t"
                     "selp.b32 %0, 1, 0, p;\n\t}" : "=r"(done) : "r"(mb), "r"(parity) : "memory");
    }
}

__device__ __forceinline__ void ldsm4(uint32_t& r0, uint32_t& r1, uint32_t& r2,
                                      uint32_t& r3, uint32_t addr) {
    asm volatile("ldmatrix.sync.aligned.m8n8.x4.shared.b16 {%0,%1,%2,%3}, [%4];"
                 : "=r"(r0), "=r"(r1), "=r"(r2), "=r"(r3) : "r"(addr));
}
__device__ __forceinline__ void mma8(float c[4], const uint32_t a[4], const uint32_t b[2]) {
    asm volatile("mma.sync.aligned.m16n8k8.row.col.f32.tf32.tf32.f32 "
                 "{%0,%1,%2,%3}, {%4,%5,%6,%7}, {%8,%9}, {%0,%1,%2,%3};"
                 : "+f"(c[0]), "+f"(c[1]), "+f"(c[2]), "+f"(c[3])
                 : "r"(a[0]), "r"(a[1]), "r"(a[2]), "r"(a[3]),
                   "r"(b[0]), "r"(b[1]));
}

// mbarrier addresses: full[s] at sb+8+s*16, empty[s] at sb+8+s*16+8
#define MB_FULL(sb, s)  ((sb) + 8 + (uint32_t)(s) * 16)
#define MB_EMPTY(sb, s) ((sb) + 8 + (uint32_t)(s) * 16 + 8)

// Consume one KC=32 stage: 4 k8 steps, each 6 ldmatrix.x4 + 16 mma per warp.
__device__ __forceinline__ void consume_stage(uint32_t sbase, int st,
                                              const uint32_t aOff[2],
                                              const uint32_t bOff[4],
                                              float acc[2][8][4])
{
    const uint32_t aB = sbase + RING_OFF + (uint32_t)st * STAGE_BYTES;
    const uint32_t bB = aB + NSTAGE * STAGE_BYTES;
#pragma unroll
    for (int ks = 0; ks < 4; ks++) {
        const int k8 = ks * 8;
        uint32_t af[2][4], bf[8][2];
#pragma unroll
        for (int i = 0; i < 2; i++)
            ldsm4(af[i][0], af[i][1], af[i][2], af[i][3], aB + (aOff[i] + k8) * 4);
#pragma unroll
        for (int jj = 0; jj < 4; jj++) {
            uint32_t r0, r1, r2, r3;
            ldsm4(r0, r1, r2, r3, bB + (bOff[jj] + k8) * 4);
            bf[2 * jj][0] = r0;  bf[2 * jj][1] = r1;
            bf[2 * jj + 1][0] = r2;  bf[2 * jj + 1][1] = r3;
        }
#pragma unroll
        for (int i = 0; i < 2; i++)
#pragma unroll
            for (int j = 0; j < 8; j++) mma8(acc[i][j], af[i], bf[j]);
    }
}

__device__ __forceinline__ void frag_offsets(int warp, int lane,
                                             uint32_t aOff[2], uint32_t bOff[4],
                                             int& warpM, int& warpN)
{
    warpM = (warp & 3) * 32;
    warpN = (warp >> 2) * 64;
    const int l7 = lane & 7, b3 = (lane >> 3) & 1, b4 = (lane >> 4) & 1;
#pragma unroll
    for (int i = 0; i < 2; i++)
        aOff[i] = (uint32_t)((warpM + i * 16 + l7 + b3 * 8) * LDK + b4 * 4);
#pragma unroll
    for (int jj = 0; jj < 4; jj++)
        bOff[jj] = (uint32_t)((warpN + jj * 16 + b4 * 8 + l7) * LDK + b3 * 4);
}

// ---------------------------------------------------------------------------
// Kernel 0: tf32-round W once (makes the W operand exact under in-MMA RZ).
// ---------------------------------------------------------------------------
__global__ __launch_bounds__(256) void round_w(const float* __restrict__ W)
{
    int i = blockIdx.x * 256 + threadIdx.x;     // float4 index
    float4 v = ((const float4*)W)[i];
    v.x = f2tff(v.x); v.y = f2tff(v.y); v.z = f2tff(v.z); v.w = f2tff(v.w);
    ((float4*)g_w_rna)[i] = v;
}

// ---------------------------------------------------------------------------
// Kernel 1: projection + L2 normalize — WARP-SPECIALIZED.
// 320 threads: warps 0-7 consumers (4m x 2n, block tile 128x128, KC=32,
// 3-stage ring), warps 8-9 producers (all cp.async). mbarrier full/empty
// handshake; consumers never touch block-wide barriers in the mainloop.
// Mask folded into epilogue scale; embeddings written tf32-rounded.
// ---------------------------------------------------------------------------
__global__ __launch_bounds__(320, 2) void proj_tc(
    const float* __restrict__ Xq, const int* __restrict__ Mq,
    const float* __restrict__ Xd, const int* __restrict__ Md,
    float* __restrict__ Eq, float* __restrict__ Ed)
{
    extern __shared__ char smem[];
    const uint32_t sbase = s2u(smem);
    const int tid  = threadIdx.x;
    const int lane = tid & 31;
    const int warp = tid >> 5;

    const bool isQ = blockIdx.x < NBLK_Q;
    const int  rb  = isQ ? blockIdx.x : (blockIdx.x - NBLK_Q);
    const int  row0 = rb * 128;
    const float* X = isQ ? Xq : Xd;
    const int*   M = isQ ? Mq : Md;
    float*       E = isQ ? Eq : Ed;
    const float* gA = X + (size_t)row0 * HDIM;
    const float* gB = g_w_rna;

    if (tid == 0) {
#pragma unroll
        for (int s = 0; s < NSTAGE; s++) {
            MBARRIER_INIT(MB_FULL(sbase, s), 64);    // 64 producer threads
            MBARRIER_INIT(MB_EMPTY(sbase, s), 256);  // 256 consumer threads
        }
    }
    __syncthreads();

    const int NC = HDIM / KC;   // 24

    if (warp >= 8) {
        // ---------------- PRODUCER (warps 8,9; 64 threads) ----------------
        const int ptid = tid - 256;            // [0,64)
        int st = 0, ph = 1;                    // empty-wait cursor (first pass free)
        for (int m = 0; m < NC; m++) {
            mbar_wait(MB_EMPTY(sbase, st), (uint32_t)ph);
            const float* a = gA + m * KC;
            const float* b = gB + m * KC;
            const uint32_t smA = sbase + RING_OFF + (uint32_t)st * STAGE_BYTES;
            const uint32_t smB = smA + NSTAGE * STAGE_BYTES;
#pragma unroll
            for (int i = 0; i < 16; i++) {
                int idx = ptid + i * 64;       // [0,1024)
                int r = idx >> 3;              // [0,128)
                int kq = (idx & 7) * 4;
                uint32_t off = (uint32_t)(r * LDK + kq) * 4;
                cp16(smA + off, a + (size_t)r * HDIM + kq);
                cp16(smB + off, b + (size_t)r * HDIM + kq);
            }
            CP_COMMIT();
            if (m >= 2) {                      // group for stage m-2 retired
                CP_WAIT(2);
                MBARRIER_ARRIVE(MB_FULL(sbase, (m - 2) % NSTAGE));
            }
            if (++st == NSTAGE) { st = 0; ph ^= 1; }
        }
        CP_WAIT(1);
        MBARRIER_ARRIVE(MB_FULL(sbase, (NC - 2) % NSTAGE));
        CP_WAIT(0);
        MBARRIER_ARRIVE(MB_FULL(sbase, (NC - 1) % NSTAGE));
        return;   // producers exit; consumers use named barrier only
    }

    // ---------------- CONSUMER (warps 0-7; 256 threads) ----------------
    uint32_t aOff[2], bOff[4];
    int warpM, warpN;
    frag_offsets(warp, lane, aOff, bOff, warpM, warpN);
    const int wn = warp >> 2;
    const int g = lane >> 2, tig = lane & 3;

    float acc[2][8][4];
#pragma unroll
    for (int i = 0; i < 2; i++)
#pragma unroll
        for (int j = 0; j < 8; j++)
#pragma unroll
            for (int e = 0; e < 4; e++) acc[i][j][e] = 0.f;

    {
        int st = 0, ph = 0;
        for (int k = 0; k < NC; k++) {
            mbar_wait(MB_FULL(sbase, st), (uint32_t)ph);
            consume_stage(sbase, st, aOff, bOff, acc);
            MBARRIER_ARRIVE(MB_EMPTY(sbase, st));
            if (++st == NSTAGE) { st = 0; ph ^= 1; }
        }
    }
    asm volatile("bar.sync 1, 256;" ::: "memory");   // consumers only

    // ---- fused L2 normalize (mask folded into scale) ----
    float* ssb = (float*)(smem + RING_OFF);   // [2][128]
#pragma unroll
    for (int i = 0; i < 2; i++) {
        float sl = 0.f, sh = 0.f;
#pragma unroll
        for (int j = 0; j < 8; j++) {
            sl += acc[i][j][0] * acc[i][j][0] + acc[i][j][1] * acc[i][j][1];
            sh += acc[i][j][2] * acc[i][j][2] + acc[i][j][3] * acc[i][j][3];
        }
        sl += __shfl_xor_sync(0xffffffffu, sl, 1);
        sl += __shfl_xor_sync(0xffffffffu, sl, 2);
        sh += __shfl_xor_sync(0xffffffffu, sh, 1);
        sh += __shfl_xor_sync(0xffffffffu, sh, 2);
        if (tig == 0) {
            ssb[wn * 128 + warpM + i * 16 + g]     = sl;
            ssb[wn * 128 + warpM + i * 16 + 8 + g] = sh;
        }
    }
    asm volatile("bar.sync 1, 256;" ::: "memory");
#pragma unroll
    for (int i = 0; i < 2; i++) {
        const int rl = warpM + i * 16 + g;
        const int rh = rl + 8;
        const float tl = ssb[rl] + ssb[128 + rl];
        const float th = ssb[rh] + ssb[128 + rh];
        const float scl = (float)M[row0 + rl] / fmaxf(sqrtf(tl), 1e-12f);
        const float sch = (float)M[row0 + rh] / fmaxf(sqrtf(th), 1e-12f);
#pragma unroll
        for (int j = 0; j < 8; j++) {
            float2 v;
            v.x = f2tff(acc[i][j][0] * scl); v.y = f2tff(acc[i][j][1] * scl);
            *(float2*)&E[(size_t)(row0 + rl) * DDIM + warpN + j * 8 + tig * 2] = v;
            v.x = f2tff(acc[i][j][2] * sch); v.y = f2tff(acc[i][j][3] * sch);
            *(float2*)&E[(size_t)(row0 + rh) * DDIM + warpN + j * 8 + tig * 2] = v;
        }
    }
}

// ---------------------------------------------------------------------------
// Kernel 2: per-batch similarity + partial max (tf32 mma.sync, KC=32 ring).
// Block (b, jc): [128 q x 128 docs], K = 128 (4 chunks of 32).  (R5 form.)
// ---------------------------------------------------------------------------
__global__ __launch_bounds__(256, 2) void maxsim_tc()
{
    extern __shared__ char smem[];
    const uint32_t sbase = s2u(smem);
    const int tid  = threadIdx.x;
    const int lane = tid & 31;
    const int warp = tid >> 5;
    const int b  = blockIdx.x;
    const int jc = blockIdx.y;

    const float* q = g_q_emb + (size_t)b * SQ * DDIM;
    const float* d = g_d_emb + ((size_t)b * SD + (size_t)jc * 128) * DDIM;

    uint32_t aOff[2], bOff[4];
    int warpM, warpN;
    frag_offsets(warp, lane, aOff, bOff, warpM, warpN);
    const int wn = warp >> 2;
    const int g = lane >> 2, tig = lane & 3;

    float acc[2][8][4];
#pragma unroll
    for (int i = 0; i < 2; i++)
#pragma unroll
        for (int j = 0; j < 8; j++)
#pragma unroll
            for (int e = 0; e < 4; e++) acc[i][j][e] = 0.f;

    auto load_stage = [&](int st, int kchunk) {
        const float* a = q + kchunk * KC;
        const float* dd = d + kchunk * KC;
        const uint32_t smA = sbase + RING_OFF + (uint32_t)st * STAGE_BYTES;
        const uint32_t smB = smA + NSTAGE * STAGE_BYTES;
#pragma unroll
        for (int i = 0; i < 4; i++) {
            int idx = tid + i * 256;
            int r = idx >> 3;
            int kq = (idx & 7) * 4;
            uint32_t off = (uint32_t)(r * LDK + kq) * 4;
            cp16(smA + off, a + (size_t)r * DDIM + kq);
            cp16(smB + off, dd + (size_t)r * DDIM + kq);
        }
    };

    load_stage(0, 0); CP_COMMIT();
    load_stage(1, 1); CP_COMMIT();

    const int NC = DDIM / KC;   // 4
    int st = 0, stn = 2;
    for (int k = 0; k < NC; k++) {
        CP_WAIT(1);
        __syncthreads();
        const int m = k + 2;
        if (m < NC) { load_stage(stn, m); CP_COMMIT(); }
        consume_stage(sbase, st, aOff, bOff, acc);
        st = (st + 1 == NSTAGE) ? 0 : st + 1;
        stn = (stn + 1 == NSTAGE) ? 0 : stn + 1;
    }
    __syncthreads();

    // ---- row max over this 128-doc chunk ----
    float* mxb = (float*)(smem + RING_OFF);   // [2][128]
#pragma unroll
    for (int i = 0; i < 2; i++) {
        float ml = acc[i][0][0], mh = acc[i][0][2];
#pragma unroll
        for (int j = 0; j < 8; j++) {
            ml = fmaxf(ml, fmaxf(acc[i][j][0], acc[i][j][1]));
            mh = fmaxf(mh, fmaxf(acc[i][j][2], acc[i][j][3]));
        }
        ml = fmaxf(ml, __shfl_xor_sync(0xffffffffu, ml, 1));
        ml = fmaxf(ml, __shfl_xor_sync(0xffffffffu, ml, 2));
        mh = fmaxf(mh, __shfl_xor_sync(0xffffffffu, mh, 1));
        mh = fmaxf(mh, __shfl_xor_sync(0xffffffffu, mh, 2));
        if (tig == 0) {
            mxb[wn * 128 + warpM + i * 16 + g]     = ml;
            mxb[wn * 128 + warpM + i * 16 + 8 + g] = mh;
        }
    }
    __syncthreads();
    if (tid < 128)
        g_pmax[((size_t)b * NJCHUNK + jc) * SQ + tid] =
            fmaxf(mxb[tid], mxb[128 + tid]);
}

// ---------------------------------------------------------------------------
// Kernel 3: finalize. out[b] = sum_i max_jc pmax[b, jc, i]
// ---------------------------------------------------------------------------
__global__ __launch_bounds__(128) void finalize_kernel(float* __restrict__ out)
{
    const int b = blockIdx.x;
    const int i = threadIdx.x;
    float m = g_pmax[((size_t)b * NJCHUNK + 0) * SQ + i];
#pragma unroll
    for (int jc = 1; jc < NJCHUNK; jc++)
        m = fmaxf(m, g_pmax[((size_t)b * NJCHUNK + jc) * SQ + i]);
#pragma unroll
    for (int o = 16; o > 0; o >>= 1)
        m += __shfl_xor_sync(0xffffffffu, m, o, 32);
    __shared__ float s[4];
    if ((i & 31) == 0) s[i >> 5] = m;
    __syncthreads();
    if (i == 0) out[b] = s[0] + s[1] + s[2] + s[3];
}

// ---------------------------------------------------------------------------
extern "C" void kernel_launch(void* const* d_in, const int* in_sizes, int n_in,
                              void* d_out, int out_size)
{
    const float* qh = (const float*)d_in[0];   // [64,128,768]
    const int*   qm = (const int*)  d_in[1];   // [64,128]
    const float* dh = (const float*)d_in[2];   // [64,1024,768]
    const int*   dm = (const int*)  d_in[3];   // [64,1024]
    const float* W  = (const float*)d_in[4];   // [128,768]
    float* out = (float*)d_out;                // [64]

    float *gq = nullptr, *gd = nullptr;
    cudaGetSymbolAddress((void**)&gq, g_q_emb);
    cudaGetSymbolAddress((void**)&gd, g_d_emb);

    cudaFuncSetAttribute(proj_tc, cudaFuncAttributeMaxDynamicSharedMemorySize, SMEM_BYTES);
    cudaFuncSetAttribute(maxsim_tc, cudaFuncAttributeMaxDynamicSharedMemorySize, SMEM_BYTES);

    round_w<<<(DDIM * HDIM / 4) / 256, 256>>>(W);
    proj_tc<<<NBLK_Q + NBLK_D, 320, SMEM_BYTES>>>(qh, qm, dh, dm, gq, gd);
    maxsim_tc<<<dim3(BATCH, NJCHUNK), 256, SMEM_BYTES>>>();
    finalize_kernel<<<BATCH, 128>>>(out);
}